// round 11
// baseline (speedup 1.0000x reference)
#include <cuda_runtime.h>

// SpikeFP32LayerNorm: row-wise LayerNorm (no affine) over 8192 rows x 4096 fp32.
// Converged memory config: 256 thr/CTA, one row/CTA, 4x float4 per thread
// (MLP=4 sweet spot), evict-first streaming both directions, 8-CTA/SM
// residency, FFMA epilogue. This round: SINGLE-barrier reduction — after the
// warp butterfly, every lane loads spart[lid&7] (8 partials replicated per
// 8-lane group) and a 3-round butterfly gives every lane the row total; each
// thread computes rsqrt+NR redundantly. Removes the 2nd __syncthreads and the
// warp-0 broadcast round-trip. (redux.f32 is NOT supported on sm_103.)
// Trajectory: 38.7 -> 34.9us; ~76% of 8 TB/s spec (mixed R/W stream).

#define ROWS  8192
#define NCOLS 4096
#define TPB   256            // 8 warps; 4x float4 per thread

__global__ __launch_bounds__(TPB, 8)
void spike_ln_kernel(const float* __restrict__ x, float* __restrict__ out) {
    const int tid = threadIdx.x;
    const int row = blockIdx.x;
    const float4* __restrict__ xin =
        reinterpret_cast<const float4*>(x + (size_t)row * NCOLS);
    float4* __restrict__ xout =
        reinterpret_cast<float4*>(out + (size_t)row * NCOLS);

    // Four independent 128-bit evict-first loads per thread (coalesced)
    float4 v0 = __ldcs(&xin[tid]);
    float4 v1 = __ldcs(&xin[tid + TPB]);
    float4 v2 = __ldcs(&xin[tid + 2 * TPB]);
    float4 v3 = __ldcs(&xin[tid + 3 * TPB]);

    float s  = ((v0.x + v0.y) + (v0.z + v0.w)) + ((v1.x + v1.y) + (v1.z + v1.w))
             + ((v2.x + v2.y) + (v2.z + v2.w)) + ((v3.x + v3.y) + (v3.z + v3.w));
    float sq = v0.x * v0.x + v0.y * v0.y + v0.z * v0.z + v0.w * v0.w
             + v1.x * v1.x + v1.y * v1.y + v1.z * v1.z + v1.w * v1.w
             + v2.x * v2.x + v2.y * v2.y + v2.z * v2.z + v2.w * v2.w
             + v3.x * v3.x + v3.y * v3.y + v3.z * v3.z + v3.w * v3.w;

    // Stage 1: 5-round warp butterfly on both accumulators
    #pragma unroll
    for (int off = 16; off > 0; off >>= 1) {
        s  += __shfl_xor_sync(0xFFFFFFFFu, s,  off);
        sq += __shfl_xor_sync(0xFFFFFFFFu, sq, off);
    }

    __shared__ float2 spart[8];     // {sum, sumsq} per warp

    const int wid = tid >> 5;
    const int lid = tid & 31;
    if (lid == 0) spart[wid] = make_float2(s, sq);
    __syncthreads();                 // the ONLY barrier

    // Stage 2 (every warp, every lane): load the 8 partials replicated per
    // 8-lane group, 3-round butterfly -> every lane holds the row totals.
    float2 p = spart[lid & 7];
    float ts = p.x, tsq = p.y;
    #pragma unroll
    for (int off = 4; off > 0; off >>= 1) {
        ts  += __shfl_xor_sync(0xFFFFFFFFu, ts,  off);
        tsq += __shfl_xor_sync(0xFFFFFFFFu, tsq, off);
    }

    // Every thread computes the normalization constants redundantly
    const float inv_n = 1.0f / (float)NCOLS;
    const float mean  = ts * inv_n;
    float var = fmaxf(tsq * inv_n - mean * mean, 0.0f);
    float vpe = var + 1e-6f;
    float rstd = rsqrtf(vpe);
    rstd = 0.5f * rstd * (3.0f - vpe * (rstd * rstd));   // one NR polish
    const float nm = -mean * rstd;

    // Single-FFMA epilogue: o = v * rstd + nm
    float4 o0, o1, o2, o3;
    o0.x = fmaf(v0.x, rstd, nm);  o0.y = fmaf(v0.y, rstd, nm);
    o0.z = fmaf(v0.z, rstd, nm);  o0.w = fmaf(v0.w, rstd, nm);
    o1.x = fmaf(v1.x, rstd, nm);  o1.y = fmaf(v1.y, rstd, nm);
    o1.z = fmaf(v1.z, rstd, nm);  o1.w = fmaf(v1.w, rstd, nm);
    o2.x = fmaf(v2.x, rstd, nm);  o2.y = fmaf(v2.y, rstd, nm);
    o2.z = fmaf(v2.z, rstd, nm);  o2.w = fmaf(v2.w, rstd, nm);
    o3.x = fmaf(v3.x, rstd, nm);  o3.y = fmaf(v3.y, rstd, nm);
    o3.z = fmaf(v3.z, rstd, nm);  o3.w = fmaf(v3.w, rstd, nm);

    __stcs(&xout[tid],           o0);
    __stcs(&xout[tid + TPB],     o1);
    __stcs(&xout[tid + 2 * TPB], o2);
    __stcs(&xout[tid + 3 * TPB], o3);
}

extern "C" void kernel_launch(void* const* d_in, const int* in_sizes, int n_in,
                              void* d_out, int out_size) {
    const float* x = (const float*)d_in[0];
    float* out = (float*)d_out;
    spike_ln_kernel<<<ROWS, TPB>>>(x, out);
}

// round 12
// speedup vs baseline: 1.0269x; 1.0269x over previous
#include <cuda_runtime.h>

// SpikeFP32LayerNorm: row-wise LayerNorm (no affine) over 8192 rows x 4096 fp32.
// CHAMPION configuration (R9, 34.94us kernel / 43.49us dur):
//   - 256 threads/CTA, one row/CTA, 4x float4/thread (MLP=4 measured optimum)
//   - evict-first streaming loads+stores (__ldcs/__stcs)
//   - 8 CTA/SM residency (regs=32 fills the register file)
//   - two-stage reduction: warp butterfly -> smem -> warp 0 only -> broadcast.
//     RULE (learned R3+R11): post-barrier work in non-warp-0 warps must be a
//     single scalar smem read — anything more sits on every warp's
//     store-issue critical path and costs ~6us.
//   - FFMA epilogue: o = v*rstd + (-mean*rstd)
// Micro-delta vs R9: ssum/ssq merged to float2 (one LDS.64 in stage 2),
// {rstd,nm} broadcast as one float2.
// At the mixed read/write HBM wall: ~76% of 8 TB/s spec.

#define ROWS  8192
#define NCOLS 4096
#define TPB   256            // 8 warps; 4x float4 per thread

__global__ __launch_bounds__(TPB, 8)
void spike_ln_kernel(const float* __restrict__ x, float* __restrict__ out) {
    const int tid = threadIdx.x;
    const int row = blockIdx.x;
    const float4* __restrict__ xin =
        reinterpret_cast<const float4*>(x + (size_t)row * NCOLS);
    float4* __restrict__ xout =
        reinterpret_cast<float4*>(out + (size_t)row * NCOLS);

    // Four independent 128-bit evict-first loads per thread (coalesced)
    float4 v0 = __ldcs(&xin[tid]);
    float4 v1 = __ldcs(&xin[tid + TPB]);
    float4 v2 = __ldcs(&xin[tid + 2 * TPB]);
    float4 v3 = __ldcs(&xin[tid + 3 * TPB]);

    float s  = ((v0.x + v0.y) + (v0.z + v0.w)) + ((v1.x + v1.y) + (v1.z + v1.w))
             + ((v2.x + v2.y) + (v2.z + v2.w)) + ((v3.x + v3.y) + (v3.z + v3.w));
    float sq = v0.x * v0.x + v0.y * v0.y + v0.z * v0.z + v0.w * v0.w
             + v1.x * v1.x + v1.y * v1.y + v1.z * v1.z + v1.w * v1.w
             + v2.x * v2.x + v2.y * v2.y + v2.z * v2.z + v2.w * v2.w
             + v3.x * v3.x + v3.y * v3.y + v3.z * v3.z + v3.w * v3.w;

    // Stage 1: warp butterfly on both accumulators
    #pragma unroll
    for (int off = 16; off > 0; off >>= 1) {
        s  += __shfl_xor_sync(0xFFFFFFFFu, s,  off);
        sq += __shfl_xor_sync(0xFFFFFFFFu, sq, off);
    }

    __shared__ float2 spart[8];     // {sum, sumsq} per warp
    __shared__ float2 s_coef;       // {rstd, -mean*rstd}

    const int wid = tid >> 5;
    const int lid = tid & 31;
    if (lid == 0) spart[wid] = make_float2(s, sq);
    __syncthreads();

    // Stage 2: warp 0 ONLY (other warps idle at the next barrier — off the
    // critical path). One LDS.64 + 3 shuffle rounds + rsqrt.
    if (wid == 0) {
        float2 p = (lid < 8) ? spart[lid] : make_float2(0.0f, 0.0f);
        float ts = p.x, tsq = p.y;
        #pragma unroll
        for (int off = 4; off > 0; off >>= 1) {
            ts  += __shfl_xor_sync(0xFFFFFFFFu, ts,  off);
            tsq += __shfl_xor_sync(0xFFFFFFFFu, tsq, off);
        }
        if (lid == 0) {
            const float inv_n = 1.0f / (float)NCOLS;
            float mean = ts * inv_n;
            float var  = fmaxf(tsq * inv_n - mean * mean, 0.0f);
            float vpe  = var + 1e-6f;
            float y = rsqrtf(vpe);
            y = 0.5f * y * (3.0f - vpe * (y * y));   // one NR polish
            s_coef = make_float2(y, -mean * y);
        }
    }
    __syncthreads();

    // Post-barrier work in all warps: ONE scalar (float2) smem read.
    const float2 coef = s_coef;
    const float rstd = coef.x;
    const float nm   = coef.y;

    // Single-FFMA epilogue: o = v * rstd + nm
    float4 o0, o1, o2, o3;
    o0.x = fmaf(v0.x, rstd, nm);  o0.y = fmaf(v0.y, rstd, nm);
    o0.z = fmaf(v0.z, rstd, nm);  o0.w = fmaf(v0.w, rstd, nm);
    o1.x = fmaf(v1.x, rstd, nm);  o1.y = fmaf(v1.y, rstd, nm);
    o1.z = fmaf(v1.z, rstd, nm);  o1.w = fmaf(v1.w, rstd, nm);
    o2.x = fmaf(v2.x, rstd, nm);  o2.y = fmaf(v2.y, rstd, nm);
    o2.z = fmaf(v2.z, rstd, nm);  o2.w = fmaf(v2.w, rstd, nm);
    o3.x = fmaf(v3.x, rstd, nm);  o3.y = fmaf(v3.y, rstd, nm);
    o3.z = fmaf(v3.z, rstd, nm);  o3.w = fmaf(v3.w, rstd, nm);

    __stcs(&xout[tid],           o0);
    __stcs(&xout[tid + TPB],     o1);
    __stcs(&xout[tid + 2 * TPB], o2);
    __stcs(&xout[tid + 3 * TPB], o3);
}

extern "C" void kernel_launch(void* const* d_in, const int* in_sizes, int n_in,
                              void* d_out, int out_size) {
    const float* x = (const float*)d_in[0];
    float* out = (float*)d_out;
    spike_ln_kernel<<<ROWS, TPB>>>(x, out);
}

// round 13
// speedup vs baseline: 1.0390x; 1.0118x over previous
#include <cuda_runtime.h>

// SpikeFP32LayerNorm: row-wise LayerNorm (no affine) over 8192 rows x 4096 fp32.
// FINAL (champion R9: 34.94us kernel / 43.49us dur / rel_err 6.0e-8):
//   - 256 threads/CTA, one row/CTA, 4x float4/thread (MLP sweep 2/4/8 ->
//     38.2/36.0/36.2us: MLP=4 optimal)
//   - evict-first streaming loads+stores (__ldcs/__stcs; each +~0.25us)
//   - 8 CTA/SM residency (regs=32 exactly fills the 64K register file)
//   - two-stage reduction: warp butterfly -> smem -> warp-0-only stage 2 ->
//     float2 coefficient broadcast. RULE (measured twice, R3 & R11): any
//     post-barrier work beyond one scalar smem read sits on every warp's
//     store-issue critical path and costs ~2-6us.
//   - FFMA epilogue: o = v*rstd + (-mean*rstd)
//   - fp32 throughout: mean~0, var~1 for this input; NR fixed point of the
//     reference FP64 circuit equals rsqrt, matched to ~1ulp fp32 (budget 1e-3)
// At the mixed 1:1 read/write HBM wall: 6.06 TB/s = ~76% of 8 TB/s spec.
// Sweeps that did NOT help: persistence (+tail imbalance), MLP=8 (occ drop),
// single-barrier butterfly (+6us), redundant smem reduce (+1.4us),
// float2-merged partials (+0.3us), redux.f32 (unsupported on sm_103).

#define ROWS  8192
#define NCOLS 4096
#define TPB   256            // 8 warps; 4x float4 per thread

__global__ __launch_bounds__(TPB, 8)
void spike_ln_kernel(const float* __restrict__ x, float* __restrict__ out) {
    const int tid = threadIdx.x;
    const int row = blockIdx.x;
    const float4* __restrict__ xin =
        reinterpret_cast<const float4*>(x + (size_t)row * NCOLS);
    float4* __restrict__ xout =
        reinterpret_cast<float4*>(out + (size_t)row * NCOLS);

    // Four independent 128-bit evict-first loads per thread (coalesced)
    float4 v0 = __ldcs(&xin[tid]);
    float4 v1 = __ldcs(&xin[tid + TPB]);
    float4 v2 = __ldcs(&xin[tid + 2 * TPB]);
    float4 v3 = __ldcs(&xin[tid + 3 * TPB]);

    float s  = ((v0.x + v0.y) + (v0.z + v0.w)) + ((v1.x + v1.y) + (v1.z + v1.w))
             + ((v2.x + v2.y) + (v2.z + v2.w)) + ((v3.x + v3.y) + (v3.z + v3.w));
    float sq = v0.x * v0.x + v0.y * v0.y + v0.z * v0.z + v0.w * v0.w
             + v1.x * v1.x + v1.y * v1.y + v1.z * v1.z + v1.w * v1.w
             + v2.x * v2.x + v2.y * v2.y + v2.z * v2.z + v2.w * v2.w
             + v3.x * v3.x + v3.y * v3.y + v3.z * v3.z + v3.w * v3.w;

    // Stage 1: warp butterfly on both accumulators
    #pragma unroll
    for (int off = 16; off > 0; off >>= 1) {
        s  += __shfl_xor_sync(0xFFFFFFFFu, s,  off);
        sq += __shfl_xor_sync(0xFFFFFFFFu, sq, off);
    }

    __shared__ float ssum[8];
    __shared__ float ssq[8];
    __shared__ float s_rstd, s_nm;   // rstd and -mean*rstd

    const int wid = tid >> 5;
    const int lid = tid & 31;
    if (lid == 0) { ssum[wid] = s; ssq[wid] = sq; }
    __syncthreads();

    // Stage 2: warp 0 only — other warps idle at the barrier, off the
    // store-issue critical path.
    if (wid == 0) {
        float ts  = (lid < 8) ? ssum[lid] : 0.0f;
        float tsq = (lid < 8) ? ssq[lid]  : 0.0f;
        #pragma unroll
        for (int off = 4; off > 0; off >>= 1) {
            ts  += __shfl_xor_sync(0xFFFFFFFFu, ts,  off);
            tsq += __shfl_xor_sync(0xFFFFFFFFu, tsq, off);
        }
        if (lid == 0) {
            const float inv_n = 1.0f / (float)NCOLS;
            float mean = ts * inv_n;
            float var  = fmaxf(tsq * inv_n - mean * mean, 0.0f);
            float vpe  = var + 1e-6f;
            float y = rsqrtf(vpe);
            y = 0.5f * y * (3.0f - vpe * (y * y));   // one NR polish
            s_rstd = y;
            s_nm   = -mean * y;
        }
    }
    __syncthreads();

    // Post-barrier work in all warps: scalar smem reads only.
    const float rstd = s_rstd;
    const float nm   = s_nm;

    // Single-FFMA epilogue: o = v * rstd + nm
    float4 o0, o1, o2, o3;
    o0.x = fmaf(v0.x, rstd, nm);  o0.y = fmaf(v0.y, rstd, nm);
    o0.z = fmaf(v0.z, rstd, nm);  o0.w = fmaf(v0.w, rstd, nm);
    o1.x = fmaf(v1.x, rstd, nm);  o1.y = fmaf(v1.y, rstd, nm);
    o1.z = fmaf(v1.z, rstd, nm);  o1.w = fmaf(v1.w, rstd, nm);
    o2.x = fmaf(v2.x, rstd, nm);  o2.y = fmaf(v2.y, rstd, nm);
    o2.z = fmaf(v2.z, rstd, nm);  o2.w = fmaf(v2.w, rstd, nm);
    o3.x = fmaf(v3.x, rstd, nm);  o3.y = fmaf(v3.y, rstd, nm);
    o3.z = fmaf(v3.z, rstd, nm);  o3.w = fmaf(v3.w, rstd, nm);

    __stcs(&xout[tid],           o0);
    __stcs(&xout[tid + TPB],     o1);
    __stcs(&xout[tid + 2 * TPB], o2);
    __stcs(&xout[tid + 3 * TPB], o3);
}

extern "C" void kernel_launch(void* const* d_in, const int* in_sizes, int n_in,
                              void* d_out, int out_size) {
    const float* x = (const float*)d_in[0];
    float* out = (float*)d_out;
    spike_ln_kernel<<<ROWS, TPB>>>(x, out);
}